// round 2
// baseline (speedup 1.0000x reference)
#include <cuda_runtime.h>
#include <math.h>

#define BATCH 32
typedef unsigned long long ull;

// scratch (device globals: sanctioned workaround for no-alloc rule)
__device__ float g_a1[32 * 64 * 126 * 126];
__device__ float g_p1[32 * 64 * 62 * 62];
__device__ float g_a2[32 * 64 * 60 * 60];
__device__ float g_p2[32 * 64 * 29 * 29];
__device__ float g_a3[32 * 64 * 27 * 27];
__device__ float g_p3[32 * 64 * 13 * 13];
__device__ double g_dsum[64];
__device__ double g_dsq[64];
__device__ double g_xs[9];
__device__ float g_scale[4][64];
__device__ float g_bias[4][64];
__device__ float g_traw[32 * 6];
__device__ float g_theta[32 * 6];

// ---------------------------------------------------------------------------
// packed f32x2 helpers (FFMA2: 2 FMAs per issue, rt_SMSP=2 -> 128 FMA/cyc/SM)
__device__ __forceinline__ ull pack2(float lo, float hi) {
    ull r;
    asm("mov.b64 %0, {%1, %2};" : "=l"(r) : "f"(lo), "f"(hi));
    return r;
}
__device__ __forceinline__ void unpack2(ull v, float& lo, float& hi) {
    asm("mov.b64 {%0, %1}, %2;" : "=f"(lo), "=f"(hi) : "l"(v));
}
__device__ __forceinline__ ull ffma2(ull a, ull b, ull c) {
    ull d;
    asm("fma.rn.f32x2 %0, %1, %2, %3;" : "=l"(d) : "l"(a), "l"(b), "l"(c));
    return d;
}

// ---------------------------------------------------------------------------
__global__ void zero_stats_kernel() {
    int t = threadIdx.x;
    if (t < 64) { g_dsum[t] = 0.0; g_dsq[t] = 0.0; }
    if (t < 9)  { g_xs[t] = 0.0; }
}

__global__ void statsx_kernel(const float* __restrict__ x) {
    __shared__ double red[256];
    double a[9];
#pragma unroll
    for (int i = 0; i < 9; i++) a[i] = 0.0;
    for (int idx = blockIdx.x * 256 + threadIdx.x; idx < BATCH * 16384;
         idx += gridDim.x * 256) {
        int b = idx >> 14, p = idx & 16383;
        double x0 = x[(b * 3 + 0) * 16384 + p];
        double x1 = x[(b * 3 + 1) * 16384 + p];
        double x2 = x[(b * 3 + 2) * 16384 + p];
        a[0] += x0 * x0; a[1] += x0 * x1; a[2] += x0 * x2;
        a[3] += x1 * x1; a[4] += x1 * x2; a[5] += x2 * x2;
        a[6] += x0;      a[7] += x1;      a[8] += x2;
    }
#pragma unroll
    for (int q = 0; q < 9; q++) {
        red[threadIdx.x] = a[q];
        __syncthreads();
        for (int o = 128; o > 0; o >>= 1) {
            if (threadIdx.x < o) red[threadIdx.x] += red[threadIdx.x + o];
            __syncthreads();
        }
        if (threadIdx.x == 0) atomicAdd(&g_xs[q], red[0]);
        __syncthreads();
    }
}

__global__ void scalebias0_kernel(const float* __restrict__ w0,
                                  const float* __restrict__ gamma,
                                  const float* __restrict__ beta) {
    int o = threadIdx.x;
    if (o >= 64) return;
    const double N = 524288.0;
    double C00 = g_xs[0] / N, C01 = g_xs[1] / N, C02 = g_xs[2] / N;
    double C11 = g_xs[3] / N, C12 = g_xs[4] / N, C22 = g_xs[5] / N;
    double m0 = g_xs[6] / N, m1 = g_xs[7] / N, m2 = g_xs[8] / N;
    double w0v = w0[o * 3 + 0], w1v = w0[o * 3 + 1], w2v = w0[o * 3 + 2];
    double m = w0v * m0 + w1v * m1 + w2v * m2;
    double e2 = w0v * w0v * C00 + w1v * w1v * C11 + w2v * w2v * C22 +
                2.0 * (w0v * w1v * C01 + w0v * w2v * C02 + w1v * w2v * C12);
    double var = e2 - m * m;
    double sc = (double)gamma[o] / sqrt(var + 1e-5);
    g_scale[0][o] = (float)sc;
    g_bias[0][o] = (float)((double)beta[o] - m * sc);
}

__global__ void stats_kernel(const float* __restrict__ src, int HW) {
    __shared__ double r1[256], r2[256];
    int bc = blockIdx.x;
    int c = bc & 63;
    const float* sb = src + (size_t)bc * HW;
    double s = 0.0, q = 0.0;
    for (int i = threadIdx.x; i < HW; i += 256) {
        double v = sb[i];
        s += v; q += v * v;
    }
    r1[threadIdx.x] = s; r2[threadIdx.x] = q;
    __syncthreads();
    for (int o = 128; o > 0; o >>= 1) {
        if (threadIdx.x < o) {
            r1[threadIdx.x] += r1[threadIdx.x + o];
            r2[threadIdx.x] += r2[threadIdx.x + o];
        }
        __syncthreads();
    }
    if (threadIdx.x == 0) {
        atomicAdd(&g_dsum[c], r1[0]);
        atomicAdd(&g_dsq[c], r2[0]);
    }
}

__global__ void scalebias_kernel(int l, const float* __restrict__ gamma,
                                 const float* __restrict__ beta, double N) {
    int c = threadIdx.x;
    if (c >= 64) return;
    double m = g_dsum[c] / N;
    double var = g_dsq[c] / N - m * m;
    double sc = (double)gamma[c] / sqrt(var + 1e-5);
    g_scale[l][c] = (float)sc;
    g_bias[l][c] = (float)((double)beta[c] - m * sc);
}

// ---------------------------------------------------------------------------
// packed conv inner: 8 out-channels x (2 rows x 2 col-pairs) per thread.
// ws2 holds duplicated weight pairs (w,w); one LDS.64 = broadcast pair.
__device__ __forceinline__ void conv_tile_accum2(const float* __restrict__ in_s,
                                                 const ull* __restrict__ ws2,
                                                 ull acc[8][4], int cg, int ry,
                                                 int cx) {
    ull pin[4][5];
#pragma unroll
    for (int r = 0; r < 4; r++) {
        const float* ip = &in_s[(ry + r) * 20 + cx];
        float v0 = ip[0], v1 = ip[1], v2 = ip[2], v3 = ip[3], v4 = ip[4],
              v5 = ip[5];
        pin[r][0] = pack2(v0, v1);
        pin[r][1] = pack2(v1, v2);
        pin[r][2] = pack2(v2, v3);
        pin[r][3] = pack2(v3, v4);
        pin[r][4] = pack2(v4, v5);
    }
#pragma unroll
    for (int ch = 0; ch < 8; ch++) {
        const ull* wp = &ws2[(cg * 8 + ch) * 10];
#pragma unroll
        for (int t = 0; t < 9; t++) {
            const int i = t / 3, j = t % 3;
            ull wt = wp[t];
#pragma unroll
            for (int r = 0; r < 2; r++) {
#pragma unroll
                for (int p = 0; p < 2; p++) {
                    acc[ch][r * 2 + p] =
                        ffma2(pin[r + i][2 * p + j], wt, acc[ch][r * 2 + p]);
                }
            }
        }
    }
}

// conv1: recompute conv0+bn0+relu per tile from x, then 3x3 conv. Double-buffered.
__global__ __launch_bounds__(256, 2) void conv1_kernel(
    const float* __restrict__ x, const float* __restrict__ w0,
    const float* __restrict__ w1) {
    __shared__ float xs[3][18 * 20];
    __shared__ float in_s[2][18 * 20];
    __shared__ ull ws2[2][64 * 10];
    const int b = blockIdx.y;
    const int tx = blockIdx.x & 7, ty = blockIdx.x >> 3;
    const int oy0 = ty * 16, ox0 = tx * 16;
    const int tid = threadIdx.x;
    const int cg = tid >> 5;
    const int sp = tid & 31;
    const int ry = (sp >> 2) * 2, cx = (sp & 3) * 4;

    ull acc[8][4];
#pragma unroll
    for (int i = 0; i < 8; i++)
#pragma unroll
        for (int j = 0; j < 4; j++) acc[i][j] = 0ULL;

    for (int idx = tid; idx < 3 * 324; idx += 256) {
        int c = idx / 324, p = idx - c * 324;
        int iy = p / 18, ix = p - iy * 18;
        int gy = oy0 + iy, gx = ox0 + ix;
        float v = 0.f;
        if (gy < 128 && gx < 128) v = x[((b * 3 + c) * 128 + gy) * 128 + gx];
        xs[c][iy * 20 + ix] = v;
    }
    __syncthreads();

    // stage function inlined: buffer bf gets channel c
    auto stage = [&](int c, int bf) {
        float a0 = w0[c * 3 + 0], a1 = w0[c * 3 + 1], a2 = w0[c * 3 + 2];
        float scl = g_scale[0][c], bia = g_bias[0][c];
        for (int idx = tid; idx < 324; idx += 256) {
            int iy = idx / 18, ix = idx - iy * 18;
            int o = iy * 20 + ix;
            float v = xs[0][o] * a0 + xs[1][o] * a1 + xs[2][o] * a2;
            in_s[bf][o] = fmaxf(fmaf(v, scl, bia), 0.f);
        }
        for (int idx = tid; idx < 576; idx += 256) {
            int o = idx / 9, t = idx - o * 9;
            float w = w1[(o * 64 + c) * 9 + t];
            ws2[bf][o * 10 + t] = pack2(w, w);
        }
    };

    stage(0, 0);
    __syncthreads();
    for (int cin = 0; cin < 64; cin++) {
        int cur = cin & 1;
        if (cin + 1 < 64) stage(cin + 1, cur ^ 1);
        conv_tile_accum2(in_s[cur], ws2[cur], acc, cg, ry, cx);
        __syncthreads();
    }

#pragma unroll
    for (int ch = 0; ch < 8; ch++) {
        const int och = cg * 8 + ch;
        float* db = g_a1 + ((size_t)(b * 64 + och)) * 126 * 126;
#pragma unroll
        for (int r = 0; r < 2; r++) {
            int oy = oy0 + ry + r;
            if (oy >= 126) continue;
#pragma unroll
            for (int p = 0; p < 2; p++) {
                float v0, v1;
                unpack2(acc[ch][r * 2 + p], v0, v1);
                int ox = ox0 + cx + 2 * p;
                if (ox < 126) db[oy * 126 + ox] = v0;
                if (ox + 1 < 126) db[oy * 126 + ox + 1] = v1;
            }
        }
    }
}

// generic 3x3 conv, bn+relu of layer `lidx` applied on load. Double-buffered.
template <int IH>
__global__ __launch_bounds__(256, 2) void conv3x3_kernel(
    const float* __restrict__ src, const float* __restrict__ wconv,
    float* __restrict__ dst, int lidx) {
    constexpr int OH = IH - 2;
    constexpr int TX = (OH + 15) / 16;
    __shared__ float in_s[2][18 * 20];
    __shared__ ull ws2[2][64 * 10];
    const int b = blockIdx.y;
    const int tx = blockIdx.x % TX, ty = blockIdx.x / TX;
    const int oy0 = ty * 16, ox0 = tx * 16;
    const int tid = threadIdx.x;
    const int cg = tid >> 5;
    const int sp = tid & 31;
    const int ry = (sp >> 2) * 2, cx = (sp & 3) * 4;

    ull acc[8][4];
#pragma unroll
    for (int i = 0; i < 8; i++)
#pragma unroll
        for (int j = 0; j < 4; j++) acc[i][j] = 0ULL;

    auto stage = [&](int c, int bf) {
        float scl = g_scale[lidx][c], bia = g_bias[lidx][c];
        const float* sb = src + ((size_t)(b * 64 + c)) * IH * IH;
        for (int idx = tid; idx < 324; idx += 256) {
            int iy = idx / 18, ix = idx - iy * 18;
            int gy = oy0 + iy, gx = ox0 + ix;
            float v = 0.f;
            if (gy < IH && gx < IH) v = sb[gy * IH + gx];
            in_s[bf][iy * 20 + ix] = fmaxf(fmaf(v, scl, bia), 0.f);
        }
        for (int idx = tid; idx < 576; idx += 256) {
            int o = idx / 9, t = idx - o * 9;
            float w = wconv[(o * 64 + c) * 9 + t];
            ws2[bf][o * 10 + t] = pack2(w, w);
        }
    };

    stage(0, 0);
    __syncthreads();
    for (int cin = 0; cin < 64; cin++) {
        int cur = cin & 1;
        if (cin + 1 < 64) stage(cin + 1, cur ^ 1);
        conv_tile_accum2(in_s[cur], ws2[cur], acc, cg, ry, cx);
        __syncthreads();
    }

#pragma unroll
    for (int ch = 0; ch < 8; ch++) {
        const int och = cg * 8 + ch;
        float* db = dst + ((size_t)(b * 64 + och)) * OH * OH;
#pragma unroll
        for (int r = 0; r < 2; r++) {
            int oy = oy0 + ry + r;
            if (oy >= OH) continue;
#pragma unroll
            for (int p = 0; p < 2; p++) {
                float v0, v1;
                unpack2(acc[ch][r * 2 + p], v0, v1);
                int ox = ox0 + cx + 2 * p;
                if (ox < OH) db[oy * OH + ox] = v0;
                if (ox + 1 < OH) db[oy * OH + ox + 1] = v1;
            }
        }
    }
}

// maxpool 3x3 stride 2
template <int CH, int PH>
__global__ void pool_kernel(const float* __restrict__ src,
                            float* __restrict__ dst) {
    int idx = blockIdx.x * blockDim.x + threadIdx.x;
    int total = BATCH * 64 * PH * PH;
    if (idx >= total) return;
    int px = idx % PH;
    int py = (idx / PH) % PH;
    int bc = idx / (PH * PH);
    const float* sb = src + (size_t)bc * CH * CH + (2 * py) * CH + 2 * px;
    float m = sb[0];
#pragma unroll
    for (int i = 0; i < 3; i++)
#pragma unroll
        for (int j = 0; j < 3; j++) m = fmaxf(m, sb[i * CH + j]);
    dst[idx] = m;
}

// ---------------------------------------------------------------------------
__global__ void fc_kernel(const float* __restrict__ Wreg,
                          const float* __restrict__ breg) {
    __shared__ float red[256];
    int j = blockIdx.x % 6, b = blockIdx.x / 6;
    const float* pb = g_p3 + (size_t)b * 10816;
    const float* wb = Wreg + (size_t)j * 10816;
    float s = 0.f;
    for (int k = threadIdx.x; k < 10816; k += 256) {
        int c = k / 169;
        float v = fmaxf(fmaf(pb[k], g_scale[3][c], g_bias[3][c]), 0.f);
        s += v * wb[k];
    }
    red[threadIdx.x] = s;
    __syncthreads();
    for (int o = 128; o > 0; o >>= 1) {
        if (threadIdx.x < o) red[threadIdx.x] += red[threadIdx.x + o];
        __syncthreads();
    }
    if (threadIdx.x == 0) g_traw[b * 6 + j] = red[0] + breg[j];
}

__global__ void sn_kernel(const float* __restrict__ u0,
                          const float* __restrict__ v0) {
    if (threadIdx.x != 0 || blockIdx.x != 0) return;
    float u[2] = {u0[0], u0[1]};
    float v[3] = {v0[0], v0[1], v0[2]};
    for (int b = 0; b < 32; b++) {
        float W[6];
#pragma unroll
        for (int i = 0; i < 6; i++) W[i] = g_traw[b * 6 + i];
#pragma unroll
        for (int it = 0; it < 4; it++) {
            float nv[3];
#pragma unroll
            for (int j = 0; j < 3; j++) nv[j] = W[j] * u[0] + W[3 + j] * u[1];
            float n = sqrtf(nv[0] * nv[0] + nv[1] * nv[1] + nv[2] * nv[2]);
            n = fmaxf(n, 1e-12f);
#pragma unroll
            for (int j = 0; j < 3; j++) v[j] = nv[j] / n;
            float nu0 = W[0] * v[0] + W[1] * v[1] + W[2] * v[2];
            float nu1 = W[3] * v[0] + W[4] * v[1] + W[5] * v[2];
            n = sqrtf(nu0 * nu0 + nu1 * nu1);
            n = fmaxf(n, 1e-12f);
            u[0] = nu0 / n; u[1] = nu1 / n;
        }
        float Wv0 = W[0] * v[0] + W[1] * v[1] + W[2] * v[2];
        float Wv1 = W[3] * v[0] + W[4] * v[1] + W[5] * v[2];
        float sigma = u[0] * Wv0 + u[1] * Wv1;
#pragma unroll
        for (int i = 0; i < 6; i++) g_theta[b * 6 + i] = W[i] / sigma;
    }
}

__global__ void sample_kernel(const float* __restrict__ x,
                              float* __restrict__ out) {
    int idx = blockIdx.x * 256 + threadIdx.x;
    if (idx >= BATCH * 16384) return;
    int b = idx >> 14, p = idx & 16383;
    int h = p >> 7, w = p & 127;
    const float* th = &g_theta[b * 6];
    float xsc = (2.f * w + 1.f) / 128.f - 1.f;
    float ysc = (2.f * h + 1.f) / 128.f - 1.f;
    float gx = th[0] * xsc + th[1] * ysc + th[2];
    float gy = th[3] * xsc + th[4] * ysc + th[5];
    float ix = ((gx + 1.f) * 128.f - 1.f) * 0.5f;
    float iy = ((gy + 1.f) * 128.f - 1.f) * 0.5f;
    float r = fmodf(fabsf(ix + 0.5f), 256.f);
    ix = (r > 128.f ? 256.f - r : r) - 0.5f;
    ix = fminf(fmaxf(ix, 0.f), 127.f);
    r = fmodf(fabsf(iy + 0.5f), 256.f);
    iy = (r > 128.f ? 256.f - r : r) - 0.5f;
    iy = fminf(fmaxf(iy, 0.f), 127.f);
    float fx0 = floorf(ix), fy0 = floorf(iy);
    float wx = ix - fx0, wy = iy - fy0;
    int x0 = min(max((int)fx0, 0), 127), y0 = min(max((int)fy0, 0), 127);
    int x1 = min(x0 + 1, 127), y1 = min(y0 + 1, 127);
    float w00 = (1.f - wx) * (1.f - wy), w10 = wx * (1.f - wy);
    float w01 = (1.f - wx) * wy, w11 = wx * wy;
#pragma unroll
    for (int c = 0; c < 3; c++) {
        const float* xb = x + (size_t)(b * 3 + c) * 16384;
        float v = xb[y0 * 128 + x0] * w00 + xb[y0 * 128 + x1] * w10 +
                  xb[y1 * 128 + x0] * w01 + xb[y1 * 128 + x1] * w11;
        out[(size_t)(b * 3 + c) * 16384 + p] = v;
    }
}

// ---------------------------------------------------------------------------
extern "C" void kernel_launch(void* const* d_in, const int* in_sizes, int n_in,
                              void* d_out, int out_size) {
    const float* x     = (const float*)d_in[0];
    const float* w0    = (const float*)d_in[1];
    const float* w1    = (const float*)d_in[2];
    const float* w2    = (const float*)d_in[3];
    const float* w3    = (const float*)d_in[4];
    const float* gamma = (const float*)d_in[5];
    const float* beta  = (const float*)d_in[6];
    const float* Wreg  = (const float*)d_in[7];
    const float* breg  = (const float*)d_in[8];
    const float* u0    = (const float*)d_in[9];
    const float* v0    = (const float*)d_in[10];
    float* out = (float*)d_out;
    (void)n_in; (void)in_sizes; (void)out_size;

    float *pa1, *pp1, *pa2, *pp2, *pa3, *pp3;
    cudaGetSymbolAddress((void**)&pa1, g_a1);
    cudaGetSymbolAddress((void**)&pp1, g_p1);
    cudaGetSymbolAddress((void**)&pa2, g_a2);
    cudaGetSymbolAddress((void**)&pp2, g_p2);
    cudaGetSymbolAddress((void**)&pa3, g_a3);
    cudaGetSymbolAddress((void**)&pp3, g_p3);

    zero_stats_kernel<<<1, 256>>>();
    statsx_kernel<<<512, 256>>>(x);
    scalebias0_kernel<<<1, 64>>>(w0, gamma, beta);

    conv1_kernel<<<dim3(64, 32), 256>>>(x, w0, w1);
    pool_kernel<126, 62><<<(32 * 64 * 62 * 62 + 255) / 256, 256>>>(pa1, pp1);
    zero_stats_kernel<<<1, 256>>>();
    stats_kernel<<<2048, 256>>>(pp1, 62 * 62);
    scalebias_kernel<<<1, 64>>>(1, gamma + 64, beta + 64, 123008.0);

    conv3x3_kernel<62><<<dim3(16, 32), 256>>>(pp1, w2, pa2, 1);
    pool_kernel<60, 29><<<(32 * 64 * 29 * 29 + 255) / 256, 256>>>(pa2, pp2);
    zero_stats_kernel<<<1, 256>>>();
    stats_kernel<<<2048, 256>>>(pp2, 29 * 29);
    scalebias_kernel<<<1, 64>>>(2, gamma + 128, beta + 128, 26912.0);

    conv3x3_kernel<29><<<dim3(4, 32), 256>>>(pp2, w3, pa3, 2);
    pool_kernel<27, 13><<<(32 * 64 * 13 * 13 + 255) / 256, 256>>>(pa3, pp3);
    zero_stats_kernel<<<1, 256>>>();
    stats_kernel<<<2048, 256>>>(pp3, 169);
    scalebias_kernel<<<1, 64>>>(3, gamma + 192, beta + 192, 5408.0);

    fc_kernel<<<192, 256>>>(Wreg, breg);
    sn_kernel<<<1, 32>>>(u0, v0);
    sample_kernel<<<(32 * 16384 + 255) / 256, 256>>>(x, out);
}

// round 3
// speedup vs baseline: 1.1404x; 1.1404x over previous
#include <cuda_runtime.h>
#include <math.h>

#define BATCH 32

// scratch (device globals: sanctioned workaround for no-alloc rule)
__device__ float g_a1[32 * 64 * 126 * 126];
__device__ float g_p1[32 * 64 * 62 * 62];
__device__ float g_a2[32 * 64 * 60 * 60];
__device__ float g_p2[32 * 64 * 29 * 29];
__device__ float g_a3[32 * 64 * 27 * 27];
__device__ float g_p3[32 * 64 * 13 * 13];
__device__ double g_dsum[64];
__device__ double g_dsq[64];
__device__ double g_xs[9];
__device__ float g_scale[4][64];
__device__ float g_bias[4][64];
__device__ float g_traw[32 * 6];
__device__ float g_theta[32 * 6];

// ---------------------------------------------------------------------------
__global__ void zero_stats_kernel() {
    int t = threadIdx.x;
    if (t < 64) { g_dsum[t] = 0.0; g_dsq[t] = 0.0; }
    if (t < 9)  { g_xs[t] = 0.0; }
}

// second moments of x in fp32 accumulation, double only for reduction tail
__global__ void statsx_kernel(const float* __restrict__ x) {
    __shared__ float red[256];
    float a[9];
#pragma unroll
    for (int i = 0; i < 9; i++) a[i] = 0.f;
    for (int idx = blockIdx.x * 256 + threadIdx.x; idx < BATCH * 16384;
         idx += gridDim.x * 256) {
        int b = idx >> 14, p = idx & 16383;
        float x0 = x[(b * 3 + 0) * 16384 + p];
        float x1 = x[(b * 3 + 1) * 16384 + p];
        float x2 = x[(b * 3 + 2) * 16384 + p];
        a[0] = fmaf(x0, x0, a[0]); a[1] = fmaf(x0, x1, a[1]);
        a[2] = fmaf(x0, x2, a[2]); a[3] = fmaf(x1, x1, a[3]);
        a[4] = fmaf(x1, x2, a[4]); a[5] = fmaf(x2, x2, a[5]);
        a[6] += x0; a[7] += x1; a[8] += x2;
    }
#pragma unroll
    for (int q = 0; q < 9; q++) {
        red[threadIdx.x] = a[q];
        __syncthreads();
        for (int o = 128; o > 0; o >>= 1) {
            if (threadIdx.x < o) red[threadIdx.x] += red[threadIdx.x + o];
            __syncthreads();
        }
        if (threadIdx.x == 0) atomicAdd(&g_xs[q], (double)red[0]);
        __syncthreads();
    }
}

__global__ void scalebias0_kernel(const float* __restrict__ w0,
                                  const float* __restrict__ gamma,
                                  const float* __restrict__ beta) {
    int o = threadIdx.x;
    if (o >= 64) return;
    const double N = 524288.0;
    double C00 = g_xs[0] / N, C01 = g_xs[1] / N, C02 = g_xs[2] / N;
    double C11 = g_xs[3] / N, C12 = g_xs[4] / N, C22 = g_xs[5] / N;
    double m0 = g_xs[6] / N, m1 = g_xs[7] / N, m2 = g_xs[8] / N;
    double w0v = w0[o * 3 + 0], w1v = w0[o * 3 + 1], w2v = w0[o * 3 + 2];
    double m = w0v * m0 + w1v * m1 + w2v * m2;
    double e2 = w0v * w0v * C00 + w1v * w1v * C11 + w2v * w2v * C22 +
                2.0 * (w0v * w1v * C01 + w0v * w2v * C02 + w1v * w2v * C12);
    double var = e2 - m * m;
    double sc = (double)gamma[o] / sqrt(var + 1e-5);
    g_scale[0][o] = (float)sc;
    g_bias[0][o] = (float)((double)beta[o] - m * sc);
}

// per-channel mean/var: fp32 accumulation, double atomics at the end
__global__ void stats_kernel(const float* __restrict__ src, int HW) {
    __shared__ float r1[256], r2[256];
    int bc = blockIdx.x;
    int c = bc & 63;
    const float* sb = src + (size_t)bc * HW;
    float s = 0.f, q = 0.f;
    for (int i = threadIdx.x; i < HW; i += 256) {
        float v = sb[i];
        s += v;
        q = fmaf(v, v, q);
    }
    r1[threadIdx.x] = s; r2[threadIdx.x] = q;
    __syncthreads();
    for (int o = 128; o > 0; o >>= 1) {
        if (threadIdx.x < o) {
            r1[threadIdx.x] += r1[threadIdx.x + o];
            r2[threadIdx.x] += r2[threadIdx.x + o];
        }
        __syncthreads();
    }
    if (threadIdx.x == 0) {
        atomicAdd(&g_dsum[c], (double)r1[0]);
        atomicAdd(&g_dsq[c], (double)r2[0]);
    }
}

__global__ void scalebias_kernel(int l, const float* __restrict__ gamma,
                                 const float* __restrict__ beta, double N) {
    int c = threadIdx.x;
    if (c >= 64) return;
    double m = g_dsum[c] / N;
    double var = g_dsq[c] / N - m * m;
    double sc = (double)gamma[c] / sqrt(var + 1e-5);
    g_scale[l][c] = (float)sc;
    g_bias[l][c] = (float)((double)beta[c] - m * sc);
}

// ---------------------------------------------------------------------------
// conv inner: OCB out-channels x (2 rows x 4 cols) per thread, 9 taps
template <int OCB>
__device__ __forceinline__ void conv_tile_accum(const float* __restrict__ in_s,
                                                const float* __restrict__ ws,
                                                float acc[OCB][8], int cg,
                                                int ry, int cx) {
    float vin[4][6];
#pragma unroll
    for (int r = 0; r < 4; r++) {
        const float* ip = &in_s[(ry + r) * 20 + cx];
#pragma unroll
        for (int c = 0; c < 6; c++) vin[r][c] = ip[c];
    }
#pragma unroll
    for (int ch = 0; ch < OCB; ch++) {
        const float* wp = &ws[(cg * OCB + ch) * 12];
        float w[9];
#pragma unroll
        for (int t = 0; t < 9; t++) w[t] = wp[t];
#pragma unroll
        for (int r = 0; r < 2; r++) {
#pragma unroll
            for (int c = 0; c < 4; c++) {
                float s = acc[ch][r * 4 + c];
                s = fmaf(vin[r][c],     w[0], s);
                s = fmaf(vin[r][c + 1], w[1], s);
                s = fmaf(vin[r][c + 2], w[2], s);
                s = fmaf(vin[r + 1][c],     w[3], s);
                s = fmaf(vin[r + 1][c + 1], w[4], s);
                s = fmaf(vin[r + 1][c + 2], w[5], s);
                s = fmaf(vin[r + 2][c],     w[6], s);
                s = fmaf(vin[r + 2][c + 1], w[7], s);
                s = fmaf(vin[r + 2][c + 2], w[8], s);
                acc[ch][r * 4 + c] = s;
            }
        }
    }
}

// conv1: recompute conv0+bn0+relu per tile from x, then 3x3 conv
__global__ __launch_bounds__(256, 2) void conv1_kernel(
    const float* __restrict__ x, const float* __restrict__ w0,
    const float* __restrict__ w1) {
    __shared__ float xs[3][18 * 20];
    __shared__ float in_s[18 * 20];
    __shared__ float ws[64 * 12];
    const int b = blockIdx.y;
    const int tx = blockIdx.x & 7, ty = blockIdx.x >> 3;
    const int oy0 = ty * 16, ox0 = tx * 16;
    const int tid = threadIdx.x;
    const int cg = tid >> 5;
    const int sp = tid & 31;
    const int ry = (sp >> 2) * 2, cx = (sp & 3) * 4;

    float acc[8][8];
#pragma unroll
    for (int i = 0; i < 8; i++)
#pragma unroll
        for (int j = 0; j < 8; j++) acc[i][j] = 0.f;

    for (int idx = tid; idx < 3 * 324; idx += 256) {
        int c = idx / 324, p = idx - c * 324;
        int iy = p / 18, ix = p - iy * 18;
        int gy = oy0 + iy, gx = ox0 + ix;
        float v = 0.f;
        if (gy < 128 && gx < 128) v = x[((b * 3 + c) * 128 + gy) * 128 + gx];
        xs[c][iy * 20 + ix] = v;
    }

    for (int cin = 0; cin < 64; cin++) {
        __syncthreads();
        float a0 = w0[cin * 3 + 0], a1 = w0[cin * 3 + 1], a2 = w0[cin * 3 + 2];
        float scl = g_scale[0][cin], bia = g_bias[0][cin];
        for (int idx = tid; idx < 324; idx += 256) {
            int iy = idx / 18, ix = idx - iy * 18;
            int o = iy * 20 + ix;
            float v = xs[0][o] * a0 + xs[1][o] * a1 + xs[2][o] * a2;
            in_s[o] = fmaxf(fmaf(v, scl, bia), 0.f);
        }
        for (int idx = tid; idx < 576; idx += 256) {
            int o = idx / 9, t = idx - o * 9;
            ws[o * 12 + t] = w1[(o * 64 + cin) * 9 + t];
        }
        __syncthreads();
        conv_tile_accum<8>(in_s, ws, acc, cg, ry, cx);
    }

#pragma unroll
    for (int ch = 0; ch < 8; ch++) {
        const int och = cg * 8 + ch;
        float* db = g_a1 + ((size_t)(b * 64 + och)) * 126 * 126;
#pragma unroll
        for (int r = 0; r < 2; r++) {
            int oy = oy0 + ry + r;
            if (oy >= 126) continue;
#pragma unroll
            for (int c = 0; c < 4; c++) {
                int ox = ox0 + cx + c;
                if (ox < 126) db[oy * 126 + ox] = acc[ch][r * 4 + c];
            }
        }
    }
}

// generic 3x3 conv; OCB out-channels per thread-group, oc-split via blockIdx.z
template <int IH, int OCB>
__global__ __launch_bounds__(256, 2) void conv3x3_kernel(
    const float* __restrict__ src, const float* __restrict__ wconv,
    float* __restrict__ dst, int lidx) {
    constexpr int OH = IH - 2;
    constexpr int TX = (OH + 15) / 16;
    constexpr int NOC = 8 * OCB;  // out-channels per block
    __shared__ float in_s[18 * 20];
    __shared__ float ws[NOC * 12];
    const int b = blockIdx.y;
    const int oc0 = blockIdx.z * NOC;
    const int tx = blockIdx.x % TX, ty = blockIdx.x / TX;
    const int oy0 = ty * 16, ox0 = tx * 16;
    const int tid = threadIdx.x;
    const int cg = tid >> 5;
    const int sp = tid & 31;
    const int ry = (sp >> 2) * 2, cx = (sp & 3) * 4;

    float acc[OCB][8];
#pragma unroll
    for (int i = 0; i < OCB; i++)
#pragma unroll
        for (int j = 0; j < 8; j++) acc[i][j] = 0.f;

    for (int cin = 0; cin < 64; cin++) {
        __syncthreads();
        float scl = g_scale[lidx][cin], bia = g_bias[lidx][cin];
        const float* sb = src + ((size_t)(b * 64 + cin)) * IH * IH;
        for (int idx = tid; idx < 324; idx += 256) {
            int iy = idx / 18, ix = idx - iy * 18;
            int gy = oy0 + iy, gx = ox0 + ix;
            float v = 0.f;
            if (gy < IH && gx < IH) v = sb[gy * IH + gx];
            in_s[iy * 20 + ix] = fmaxf(fmaf(v, scl, bia), 0.f);
        }
        for (int idx = tid; idx < NOC * 9; idx += 256) {
            int o = idx / 9, t = idx - o * 9;
            ws[o * 12 + t] = wconv[((oc0 + o) * 64 + cin) * 9 + t];
        }
        __syncthreads();
        conv_tile_accum<OCB>(in_s, ws, acc, cg, ry, cx);
    }

#pragma unroll
    for (int ch = 0; ch < OCB; ch++) {
        const int och = oc0 + cg * OCB + ch;
        float* db = dst + ((size_t)(b * 64 + och)) * OH * OH;
#pragma unroll
        for (int r = 0; r < 2; r++) {
            int oy = oy0 + ry + r;
            if (oy >= OH) continue;
#pragma unroll
            for (int c = 0; c < 4; c++) {
                int ox = ox0 + cx + c;
                if (ox < OH) db[oy * OH + ox] = acc[ch][r * 4 + c];
            }
        }
    }
}

// maxpool 3x3 stride 2
template <int CH, int PH>
__global__ void pool_kernel(const float* __restrict__ src,
                            float* __restrict__ dst) {
    int idx = blockIdx.x * blockDim.x + threadIdx.x;
    int total = BATCH * 64 * PH * PH;
    if (idx >= total) return;
    int px = idx % PH;
    int py = (idx / PH) % PH;
    int bc = idx / (PH * PH);
    const float* sb = src + (size_t)bc * CH * CH + (2 * py) * CH + 2 * px;
    float m = sb[0];
#pragma unroll
    for (int i = 0; i < 3; i++)
#pragma unroll
        for (int j = 0; j < 3; j++) m = fmaxf(m, sb[i * CH + j]);
    dst[idx] = m;
}

// ---------------------------------------------------------------------------
__global__ void fc_kernel(const float* __restrict__ Wreg,
                          const float* __restrict__ breg) {
    __shared__ float red[256];
    int j = blockIdx.x % 6, b = blockIdx.x / 6;
    const float* pb = g_p3 + (size_t)b * 10816;
    const float* wb = Wreg + (size_t)j * 10816;
    float s = 0.f;
    for (int k = threadIdx.x; k < 10816; k += 256) {
        int c = k / 169;
        float v = fmaxf(fmaf(pb[k], g_scale[3][c], g_bias[3][c]), 0.f);
        s += v * wb[k];
    }
    red[threadIdx.x] = s;
    __syncthreads();
    for (int o = 128; o > 0; o >>= 1) {
        if (threadIdx.x < o) red[threadIdx.x] += red[threadIdx.x + o];
        __syncthreads();
    }
    if (threadIdx.x == 0) g_traw[b * 6 + j] = red[0] + breg[j];
}

__global__ void sn_kernel(const float* __restrict__ u0,
                          const float* __restrict__ v0) {
    if (threadIdx.x != 0 || blockIdx.x != 0) return;
    float u[2] = {u0[0], u0[1]};
    float v[3] = {v0[0], v0[1], v0[2]};
    for (int b = 0; b < 32; b++) {
        float W[6];
#pragma unroll
        for (int i = 0; i < 6; i++) W[i] = g_traw[b * 6 + i];
#pragma unroll
        for (int it = 0; it < 4; it++) {
            float nv[3];
#pragma unroll
            for (int j = 0; j < 3; j++) nv[j] = W[j] * u[0] + W[3 + j] * u[1];
            float n = sqrtf(nv[0] * nv[0] + nv[1] * nv[1] + nv[2] * nv[2]);
            n = fmaxf(n, 1e-12f);
#pragma unroll
            for (int j = 0; j < 3; j++) v[j] = nv[j] / n;
            float nu0 = W[0] * v[0] + W[1] * v[1] + W[2] * v[2];
            float nu1 = W[3] * v[0] + W[4] * v[1] + W[5] * v[2];
            n = sqrtf(nu0 * nu0 + nu1 * nu1);
            n = fmaxf(n, 1e-12f);
            u[0] = nu0 / n; u[1] = nu1 / n;
        }
        float Wv0 = W[0] * v[0] + W[1] * v[1] + W[2] * v[2];
        float Wv1 = W[3] * v[0] + W[4] * v[1] + W[5] * v[2];
        float sigma = u[0] * Wv0 + u[1] * Wv1;
#pragma unroll
        for (int i = 0; i < 6; i++) g_theta[b * 6 + i] = W[i] / sigma;
    }
}

__global__ void sample_kernel(const float* __restrict__ x,
                              float* __restrict__ out) {
    int idx = blockIdx.x * 256 + threadIdx.x;
    if (idx >= BATCH * 16384) return;
    int b = idx >> 14, p = idx & 16383;
    int h = p >> 7, w = p & 127;
    const float* th = &g_theta[b * 6];
    float xsc = (2.f * w + 1.f) / 128.f - 1.f;
    float ysc = (2.f * h + 1.f) / 128.f - 1.f;
    float gx = th[0] * xsc + th[1] * ysc + th[2];
    float gy = th[3] * xsc + th[4] * ysc + th[5];
    float ix = ((gx + 1.f) * 128.f - 1.f) * 0.5f;
    float iy = ((gy + 1.f) * 128.f - 1.f) * 0.5f;
    float r = fmodf(fabsf(ix + 0.5f), 256.f);
    ix = (r > 128.f ? 256.f - r : r) - 0.5f;
    ix = fminf(fmaxf(ix, 0.f), 127.f);
    r = fmodf(fabsf(iy + 0.5f), 256.f);
    iy = (r > 128.f ? 256.f - r : r) - 0.5f;
    iy = fminf(fmaxf(iy, 0.f), 127.f);
    float fx0 = floorf(ix), fy0 = floorf(iy);
    float wx = ix - fx0, wy = iy - fy0;
    int x0 = min(max((int)fx0, 0), 127), y0 = min(max((int)fy0, 0), 127);
    int x1 = min(x0 + 1, 127), y1 = min(y0 + 1, 127);
    float w00 = (1.f - wx) * (1.f - wy), w10 = wx * (1.f - wy);
    float w01 = (1.f - wx) * wy, w11 = wx * wy;
#pragma unroll
    for (int c = 0; c < 3; c++) {
        const float* xb = x + (size_t)(b * 3 + c) * 16384;
        float v = xb[y0 * 128 + x0] * w00 + xb[y0 * 128 + x1] * w10 +
                  xb[y1 * 128 + x0] * w01 + xb[y1 * 128 + x1] * w11;
        out[(size_t)(b * 3 + c) * 16384 + p] = v;
    }
}

// ---------------------------------------------------------------------------
extern "C" void kernel_launch(void* const* d_in, const int* in_sizes, int n_in,
                              void* d_out, int out_size) {
    const float* x     = (const float*)d_in[0];
    const float* w0    = (const float*)d_in[1];
    const float* w1    = (const float*)d_in[2];
    const float* w2    = (const float*)d_in[3];
    const float* w3    = (const float*)d_in[4];
    const float* gamma = (const float*)d_in[5];
    const float* beta  = (const float*)d_in[6];
    const float* Wreg  = (const float*)d_in[7];
    const float* breg  = (const float*)d_in[8];
    const float* u0    = (const float*)d_in[9];
    const float* v0    = (const float*)d_in[10];
    float* out = (float*)d_out;
    (void)n_in; (void)in_sizes; (void)out_size;

    float *pa1, *pp1, *pa2, *pp2, *pa3, *pp3;
    cudaGetSymbolAddress((void**)&pa1, g_a1);
    cudaGetSymbolAddress((void**)&pp1, g_p1);
    cudaGetSymbolAddress((void**)&pa2, g_a2);
    cudaGetSymbolAddress((void**)&pp2, g_p2);
    cudaGetSymbolAddress((void**)&pa3, g_a3);
    cudaGetSymbolAddress((void**)&pp3, g_p3);

    zero_stats_kernel<<<1, 256>>>();
    statsx_kernel<<<512, 256>>>(x);
    scalebias0_kernel<<<1, 64>>>(w0, gamma, beta);

    conv1_kernel<<<dim3(64, 32), 256>>>(x, w0, w1);
    pool_kernel<126, 62><<<(32 * 64 * 62 * 62 + 255) / 256, 256>>>(pa1, pp1);
    zero_stats_kernel<<<1, 256>>>();
    stats_kernel<<<2048, 256>>>(pp1, 62 * 62);
    scalebias_kernel<<<1, 64>>>(1, gamma + 64, beta + 64, 123008.0);

    conv3x3_kernel<62, 8><<<dim3(16, 32, 1), 256>>>(pp1, w2, pa2, 1);
    pool_kernel<60, 29><<<(32 * 64 * 29 * 29 + 255) / 256, 256>>>(pa2, pp2);
    zero_stats_kernel<<<1, 256>>>();
    stats_kernel<<<2048, 256>>>(pp2, 29 * 29);
    scalebias_kernel<<<1, 64>>>(2, gamma + 128, beta + 128, 26912.0);

    // conv3: oc-split x2 to fill the chip (256 blocks instead of 128)
    conv3x3_kernel<29, 4><<<dim3(4, 32, 2), 256>>>(pp2, w3, pa3, 2);
    pool_kernel<27, 13><<<(32 * 64 * 13 * 13 + 255) / 256, 256>>>(pa3, pp3);
    zero_stats_kernel<<<1, 256>>>();
    stats_kernel<<<2048, 256>>>(pp3, 169);
    scalebias_kernel<<<1, 64>>>(3, gamma + 192, beta + 192, 5408.0);

    fc_kernel<<<192, 256>>>(Wreg, breg);
    sn_kernel<<<1, 32>>>(u0, v0);
    sample_kernel<<<(32 * 16384 + 255) / 256, 256>>>(x, out);
}